// round 1
// baseline (speedup 1.0000x reference)
#include <cuda_runtime.h>
#include <math_constants.h>

#define THREADS 256
#define NWARPS  8
#define KD      3      // ceil(690 / 256)
#define MAXD    768    // KD * THREADS, >= D=690

// Scratch: per-sentence logits / softmax weights (N_SENT = 131072)
__device__ float g_logit[1 << 17];
// Precomputed attention_weight * relation_weight, [C, D] = 53 x 690
__device__ float g_aw[53 * 690];

__global__ void precompute_aw_kernel(const float* __restrict__ rel,
                                     const float* __restrict__ att, int n) {
    int i = blockIdx.x * blockDim.x + threadIdx.x;
    if (i < n) g_aw[i] = rel[i] * att[i];
}

__device__ __forceinline__ float warp_sum(float v) {
    #pragma unroll
    for (int o = 16; o; o >>= 1) v += __shfl_down_sync(0xffffffffu, v, o);
    return v;
}
__device__ __forceinline__ float warp_max(float v) {
    #pragma unroll
    for (int o = 16; o; o >>= 1) v = fmaxf(v, __shfl_down_sync(0xffffffffu, v, o));
    return v;
}

__global__ void __launch_bounds__(THREADS)
bag_kernel(const float* __restrict__ x,
           const float* __restrict__ rel_w,
           const float* __restrict__ bias,
           const int*   __restrict__ query,
           const int*   __restrict__ scope,
           float*       __restrict__ out,
           int D, int C)
{
    const int b     = blockIdx.x;
    const int start = scope[b];
    const int end   = scope[b + 1];
    const int cnt   = end - start;
    const int tid   = threadIdx.x;
    const int wid   = tid >> 5;
    const int lane  = tid & 31;

    __shared__ float s_red[NWARPS];
    __shared__ float s_w[THREADS];
    __shared__ float s_repre[MAXD];

    // ---------------- Pass A: per-sentence attention logits ----------------
    // warp-per-row: dot(x[i], aw[q_i]) over D, lane-strided (coalesced)
    for (int i = start + wid; i < end; i += NWARPS) {
        const int q = query[i];
        const float* __restrict__ xr = x    + (size_t)i * D;
        const float* __restrict__ ar = g_aw + (size_t)q * D;
        float p = 0.f;
        for (int d = lane; d < D; d += 32) p += xr[d] * ar[d];
        p = warp_sum(p);
        if (lane == 0) g_logit[i] = p;
    }
    __syncthreads();   // g_logit[start..end) visible block-wide

    // ---------------- segment softmax: max ----------------
    float lm = -CUDART_INF_F;
    for (int i = start + tid; i < end; i += THREADS) lm = fmaxf(lm, g_logit[i]);
    lm = warp_max(lm);
    if (lane == 0) s_red[wid] = lm;
    __syncthreads();
    if (wid == 0) {
        float v = (lane < NWARPS) ? s_red[lane] : -CUDART_INF_F;
        v = warp_max(v);
        if (lane == 0) s_red[0] = v;
    }
    __syncthreads();
    const float m = s_red[0];
    __syncthreads();   // everyone has m before s_red reuse

    // ---------------- segment softmax: sum of exp ----------------
    float ls = 0.f;
    for (int i = start + tid; i < end; i += THREADS) {
        float e = expf(g_logit[i] - m);
        g_logit[i] = e;          // store unnormalized weight
        ls += e;
    }
    ls = warp_sum(ls);
    if (lane == 0) s_red[wid] = ls;
    __syncthreads();
    if (wid == 0) {
        float v = (lane < NWARPS) ? s_red[lane] : 0.f;
        v = warp_sum(v);
        if (lane == 0) s_red[0] = v;
    }
    __syncthreads();
    const float inv_denom = 1.f / s_red[0];

    // ---------------- Pass B: bag_repre[d] = sum_i w_i * x[i,d] ----------------
    // threads own d-columns; x rows re-read from L2 (just touched in pass A)
    float acc[KD] = {0.f, 0.f, 0.f};
    for (int base = 0; base < cnt; base += THREADS) {
        __syncthreads();
        if (base + tid < cnt) s_w[tid] = g_logit[start + base + tid];
        __syncthreads();
        const int lim = min(THREADS, cnt - base);
        for (int j = 0; j < lim; j++) {
            const float wg = s_w[j];
            const float* __restrict__ xr = x + (size_t)(start + base + j) * D;
            #pragma unroll
            for (int k = 0; k < KD; k++) {
                const int d = tid + k * THREADS;
                if (d < D) acc[k] = fmaf(wg, xr[d], acc[k]);
            }
        }
    }
    #pragma unroll
    for (int k = 0; k < KD; k++) {
        const int d = tid + k * THREADS;
        if (d < D) s_repre[d] = acc[k] * inv_denom;
    }
    __syncthreads();

    // ---------------- final classifier: out[b,c] = repre . rel_w[c] + bias[c] ----
    for (int c = wid; c < C; c += NWARPS) {
        const float* __restrict__ rw = rel_w + (size_t)c * D;
        float p = 0.f;
        for (int d = lane; d < D; d += 32) p += s_repre[d] * rw[d];
        p = warp_sum(p);
        if (lane == 0) out[(size_t)b * C + c] = p + bias[c];
    }
}

extern "C" void kernel_launch(void* const* d_in, const int* in_sizes, int n_in,
                              void* d_out, int out_size)
{
    const float* x     = (const float*)d_in[0];
    const float* rel_w = (const float*)d_in[1];
    const float* att_w = (const float*)d_in[2];
    const float* bias  = (const float*)d_in[3];
    const int*   query = (const int*)  d_in[4];
    const int*   scope = (const int*)  d_in[5];

    const int C = in_sizes[3];           // 53
    const int D = in_sizes[1] / C;       // 690
    const int B = in_sizes[5] - 1;       // 8192

    const int naw = C * D;
    precompute_aw_kernel<<<(naw + 255) / 256, 256>>>(rel_w, att_w, naw);
    bag_kernel<<<B, THREADS>>>(x, rel_w, bias, query, scope, (float*)d_out, D, C);
}